// round 9
// baseline (speedup 1.0000x reference)
#include <cuda_runtime.h>
#include <cuda_bf16.h>
#include <cstdint>

// Problem constants (fixed by the reference)
#define N_NODES 50000
#define N_EDGES 800000
#define NFEAT   512
#define NHID    128
#define NCLASS  40

// Device scratch (no cudaMalloc allowed)
__device__ float g_h1[N_NODES * NHID];    // support1 = x @ W1      (25.6 MB)
__device__ float g_agg1[N_NODES * NHID];  // aggregated layer-1 out (25.6 MB)
__device__ float g_h2[N_NODES * NCLASS];  // support2 = relu(h) @ W2 (8 MB)

// CSR build scratch
__device__ int   g_count[N_NODES];        // per-dst degree
__device__ int   g_off[N_NODES + 1];      // CSR row offsets
__device__ int   g_cur[N_NODES];          // scatter cursors
__device__ int   g_src_s[N_EDGES];        // src sorted by dst
__device__ float g_w_s[N_EDGES];          // weight sorted by dst

__device__ __forceinline__ uint32_t cvt_tf32(float f) {
    uint32_t out;
    asm("cvt.rna.tf32.f32 %0, %1;" : "=r"(out) : "f"(f));
    return out;
}

__device__ __forceinline__ void mma_tf32(
    float& d0, float& d1, float& d2, float& d3,
    uint32_t a0, uint32_t a1, uint32_t a2, uint32_t a3,
    uint32_t b0, uint32_t b1)
{
    asm volatile(
        "mma.sync.aligned.m16n8k8.row.col.f32.tf32.tf32.f32 "
        "{%0,%1,%2,%3}, {%4,%5,%6,%7}, {%8,%9}, {%0,%1,%2,%3};"
        : "+f"(d0), "+f"(d1), "+f"(d2), "+f"(d3)
        : "r"(a0), "r"(a1), "r"(a2), "r"(a3), "r"(b0), "r"(b1));
}

// ===========================================================================
// GEMM1 (HMMA tf32): C[M,128] = tf32(A[M,512]) @ tf32(W1[512,128])
// CTA tile 128x128, BK=32, 8 warps, warp tile 32(M) x 64(N), frag-permuted smem
// ===========================================================================
#define G1_BK 32

__global__ __launch_bounds__(256) void gemm1_mma_kernel(
    const float* __restrict__ A, const float* __restrict__ W1,
    float* __restrict__ C, int M)
{
    __shared__ uint32_t sA[4 * 8 * 32 * 4];   // 16 KB  [ks][mt][lane][slot]
    __shared__ uint32_t sB[4 * 8 * 32 * 4];   // 16 KB  [ks][ntp][lane][slot]

    const int tid  = threadIdx.x;
    const int lane = tid & 31;
    const int wid  = tid >> 5;
    const int warp_m = wid & 3;
    const int warp_n = wid >> 2;
    const int m0 = blockIdx.x * 128;

    float acc[2][8][4];
#pragma unroll
    for (int mi = 0; mi < 2; mi++)
#pragma unroll
        for (int nt = 0; nt < 8; nt++)
#pragma unroll
            for (int j = 0; j < 4; j++) acc[mi][nt][j] = 0.0f;

    for (int k0 = 0; k0 < NFEAT; k0 += G1_BK) {
#pragma unroll
        for (int t = 0; t < 4; t++) {
            int i = tid + t * 256;
            int r = i >> 3;
            int q = i & 7;
            float4 v = make_float4(0.f, 0.f, 0.f, 0.f);
            if (m0 + r < M)
                v = *(const float4*)&A[(size_t)(m0 + r) * NFEAT + k0 + q * 4];
            uint32_t u[4] = {cvt_tf32(v.x), cvt_tf32(v.y), cvt_tf32(v.z), cvt_tf32(v.w)};
            int ks   = q >> 1;
            int mt   = r >> 4;
            int slot = ((r >> 3) & 1) + 2 * (q & 1);
            int base = ((ks * 8 + mt) * 32 + (r & 7) * 4) * 4 + slot;
#pragma unroll
            for (int j = 0; j < 4; j++) sA[base + j * 4] = u[j];
        }
#pragma unroll
        for (int t = 0; t < 4; t++) {
            int i = tid + t * 256;
            int kk = i >> 5;
            int nf = i & 31;
            float4 v = *(const float4*)&W1[(size_t)(k0 + kk) * NHID + nf * 4];
            uint32_t u[4] = {cvt_tf32(v.x), cvt_tf32(v.y), cvt_tf32(v.z), cvt_tf32(v.w)};
            int ks   = kk >> 3;
            int kc   = kk & 7;
            int ntp  = nf >> 2;
            int slot = ((nf >> 1) & 1) * 2 + (kc >> 2);
            int base = ((ks * 8 + ntp) * 32 + (nf & 1) * 16 + (kc & 3)) * 4 + slot;
#pragma unroll
            for (int j = 0; j < 4; j++) sB[base + j * 16] = u[j];
        }
        __syncthreads();

#pragma unroll
        for (int ks = 0; ks < 4; ks++) {
            uint4 af[2];
#pragma unroll
            for (int mi = 0; mi < 2; mi++) {
                int mt = warp_m * 2 + mi;
                af[mi] = *(const uint4*)&sA[((ks * 8 + mt) * 32 + lane) * 4];
            }
#pragma unroll
            for (int np = 0; np < 4; np++) {
                int ntp = warp_n * 4 + np;
                uint4 bf = *(const uint4*)&sB[((ks * 8 + ntp) * 32 + lane) * 4];
#pragma unroll
                for (int mi = 0; mi < 2; mi++) {
                    mma_tf32(acc[mi][np*2][0], acc[mi][np*2][1],
                             acc[mi][np*2][2], acc[mi][np*2][3],
                             af[mi].x, af[mi].y, af[mi].z, af[mi].w,
                             bf.x, bf.y);
                    mma_tf32(acc[mi][np*2+1][0], acc[mi][np*2+1][1],
                             acc[mi][np*2+1][2], acc[mi][np*2+1][3],
                             af[mi].x, af[mi].y, af[mi].z, af[mi].w,
                             bf.z, bf.w);
                }
            }
        }
        __syncthreads();
    }

#pragma unroll
    for (int mi = 0; mi < 2; mi++) {
        int r_base = m0 + warp_m * 32 + mi * 16 + (lane >> 2);
#pragma unroll
        for (int nt = 0; nt < 8; nt++) {
            int col = warp_n * 64 + nt * 8 + (lane & 3) * 2;
            if (r_base < M)
                *(float2*)&C[(size_t)r_base * NHID + col] =
                    make_float2(acc[mi][nt][0], acc[mi][nt][1]);
            if (r_base + 8 < M)
                *(float2*)&C[(size_t)(r_base + 8) * NHID + col] =
                    make_float2(acc[mi][nt][2], acc[mi][nt][3]);
        }
    }
}

// ===========================================================================
// CSR build: zero -> histogram -> scan -> scatter
// ===========================================================================
__global__ void zero_count_kernel()
{
    int i = blockIdx.x * blockDim.x + threadIdx.x;
    if (i < N_NODES) g_count[i] = 0;
}

__global__ void hist_kernel(const int* __restrict__ edst)
{
    int e = blockIdx.x * blockDim.x + threadIdx.x;
    if (e < N_EDGES) atomicAdd(&g_count[edst[e]], 1);
}

// one block of 1024 threads: exclusive scan of g_count into g_off / g_cur
__global__ __launch_bounds__(1024) void scan_kernel()
{
    __shared__ int warp_sums[32];
    const int T = 1024;
    const int CH = (N_NODES + T - 1) / T;       // 49
    const int tid = threadIdx.x;
    const int lane = tid & 31;
    const int w = tid >> 5;
    const int base = tid * CH;
    const int lim = min(base + CH, N_NODES);

    int sum = 0;
    for (int i = base; i < lim; i++) sum += g_count[i];

    // inclusive warp scan
    int v = sum;
#pragma unroll
    for (int o = 1; o < 32; o <<= 1) {
        int n = __shfl_up_sync(0xFFFFFFFFu, v, o);
        if (lane >= o) v += n;
    }
    if (lane == 31) warp_sums[w] = v;
    __syncthreads();
    if (w == 0) {
        int ws = (tid < 32) ? warp_sums[tid] : 0;
#pragma unroll
        for (int o = 1; o < 32; o <<= 1) {
            int n = __shfl_up_sync(0xFFFFFFFFu, ws, o);
            if (lane >= o) ws += n;
        }
        if (tid < 32) warp_sums[tid] = ws;
    }
    __syncthreads();

    int thread_excl = v - sum + ((w > 0) ? warp_sums[w - 1] : 0);

    int run = thread_excl;
    for (int i = base; i < lim; i++) {
        int c = g_count[i];
        g_off[i] = run;
        g_cur[i] = run;
        run += c;
    }
    if (tid == T - 1) g_off[N_NODES] = run;
}

__global__ void scatter_kernel(const int* __restrict__ esrc,
                               const int* __restrict__ edst,
                               const float* __restrict__ ew)
{
    int e = blockIdx.x * blockDim.x + threadIdx.x;
    if (e >= N_EDGES) return;
    int d = edst[e];
    int pos = atomicAdd(&g_cur[d], 1);
    g_src_s[pos] = esrc[e];
    g_w_s[pos]  = ew[e];
}

// ===========================================================================
// SpMM layer 1 (CSR): warp per dst node, segmented sum, bias fused.
// ===========================================================================
__global__ __launch_bounds__(256) void spmm1_csr_kernel(const float* __restrict__ b1)
{
    const int wid  = threadIdx.x >> 5;
    const int lane = threadIdx.x & 31;
    const int d = blockIdx.x * 8 + wid;
    if (d >= N_NODES) return;

    const int beg = g_off[d];
    const int end = g_off[d + 1];

    float4 a0 = make_float4(0.f, 0.f, 0.f, 0.f);
    float4 a1 = make_float4(0.f, 0.f, 0.f, 0.f);

    int e = beg;
    for (; e + 1 < end; e += 2) {
        int   s0 = g_src_s[e],     s1 = g_src_s[e + 1];
        float w0 = g_w_s[e],       w1 = g_w_s[e + 1];
        float4 v0 = *(const float4*)&g_h1[(size_t)s0 * NHID + lane * 4];
        float4 v1 = *(const float4*)&g_h1[(size_t)s1 * NHID + lane * 4];
        a0.x += w0 * v0.x; a0.y += w0 * v0.y; a0.z += w0 * v0.z; a0.w += w0 * v0.w;
        a1.x += w1 * v1.x; a1.y += w1 * v1.y; a1.z += w1 * v1.z; a1.w += w1 * v1.w;
    }
    if (e < end) {
        int   s0 = g_src_s[e];
        float w0 = g_w_s[e];
        float4 v0 = *(const float4*)&g_h1[(size_t)s0 * NHID + lane * 4];
        a0.x += w0 * v0.x; a0.y += w0 * v0.y; a0.z += w0 * v0.z; a0.w += w0 * v0.w;
    }

    float4 bb = *(const float4*)&b1[lane * 4];
    float4 r;
    r.x = a0.x + a1.x + bb.x;
    r.y = a0.y + a1.y + bb.y;
    r.z = a0.z + a1.z + bb.z;
    r.w = a0.w + a1.w + bb.w;
    *(float4*)&g_agg1[(size_t)d * NHID + lane * 4] = r;
}

// ===========================================================================
// GEMM2: C[M,40] = relu(H[M,128]) @ W2[128,40]
// ===========================================================================
__global__ __launch_bounds__(256) void gemm2_kernel(
    const float* __restrict__ H, const float* __restrict__ W2,
    float* __restrict__ C, int M)
{
    __shared__ float sW[NHID * NCLASS];   // [k][c]  20 KB
    __shared__ float sh[32 * 128];        // [k][node] 16 KB

    const int tid = threadIdx.x;
    const int tx = tid & 7;
    const int ty = tid >> 3;
    const int n0 = blockIdx.x * 128;

    for (int i = tid; i < (NHID * NCLASS) / 4; i += 256)
        *(float4*)&sW[i * 4] = *(const float4*)&W2[i * 4];

    float acc[4][5];
#pragma unroll
    for (int i = 0; i < 4; i++)
#pragma unroll
        for (int j = 0; j < 5; j++) acc[i][j] = 0.0f;

    for (int kc = 0; kc < 4; kc++) {
        __syncthreads();
        for (int i = tid; i < 1024; i += 256) {
            int node = i & 127;
            int kq   = i >> 7;
            float4 v = make_float4(0.f, 0.f, 0.f, 0.f);
            if (n0 + node < M) {
                v = *(const float4*)&H[(size_t)(n0 + node) * NHID + kc * 32 + kq * 4];
                v.x = fmaxf(v.x, 0.f); v.y = fmaxf(v.y, 0.f);
                v.z = fmaxf(v.z, 0.f); v.w = fmaxf(v.w, 0.f);
            }
            sh[(kq * 4 + 0) * 128 + node] = v.x;
            sh[(kq * 4 + 1) * 128 + node] = v.y;
            sh[(kq * 4 + 2) * 128 + node] = v.z;
            sh[(kq * 4 + 3) * 128 + node] = v.w;
        }
        __syncthreads();

#pragma unroll
        for (int k = 0; k < 32; k++) {
            float4 h4 = *(const float4*)&sh[k * 128 + ty * 4];
            const float* wr = &sW[(kc * 32 + k) * NCLASS + tx];
#pragma unroll
            for (int j = 0; j < 5; j++) {
                float w = wr[j * 8];
                acc[0][j] += h4.x * w;
                acc[1][j] += h4.y * w;
                acc[2][j] += h4.z * w;
                acc[3][j] += h4.w * w;
            }
        }
    }

#pragma unroll
    for (int i = 0; i < 4; i++) {
        int node = n0 + ty * 4 + i;
        if (node < M) {
#pragma unroll
            for (int j = 0; j < 5; j++)
                C[(size_t)node * NCLASS + tx + j * 8] = acc[i][j];
        }
    }
}

// ===========================================================================
// SpMM layer 2 (CSR): 10 threads per dst (one float4 chunk each), bias fused.
// Consecutive threads cover a dst's 160B row -> coalesced gathers.
// ===========================================================================
__global__ __launch_bounds__(256) void spmm2_csr_kernel(
    const float* __restrict__ b2, float* __restrict__ out)
{
    unsigned gid = blockIdx.x * blockDim.x + threadIdx.x;
    unsigned d = gid / 10;
    unsigned c = gid % 10;
    if (d >= N_NODES) return;

    const int beg = g_off[d];
    const int end = g_off[d + 1];

    float4 a0 = make_float4(0.f, 0.f, 0.f, 0.f);
    float4 a1 = make_float4(0.f, 0.f, 0.f, 0.f);

    int e = beg;
    for (; e + 1 < end; e += 2) {
        int   s0 = g_src_s[e],   s1 = g_src_s[e + 1];
        float w0 = g_w_s[e],     w1 = g_w_s[e + 1];
        float4 v0 = *(const float4*)&g_h2[(size_t)s0 * NCLASS + c * 4];
        float4 v1 = *(const float4*)&g_h2[(size_t)s1 * NCLASS + c * 4];
        a0.x += w0 * v0.x; a0.y += w0 * v0.y; a0.z += w0 * v0.z; a0.w += w0 * v0.w;
        a1.x += w1 * v1.x; a1.y += w1 * v1.y; a1.z += w1 * v1.z; a1.w += w1 * v1.w;
    }
    if (e < end) {
        int   s0 = g_src_s[e];
        float w0 = g_w_s[e];
        float4 v0 = *(const float4*)&g_h2[(size_t)s0 * NCLASS + c * 4];
        a0.x += w0 * v0.x; a0.y += w0 * v0.y; a0.z += w0 * v0.z; a0.w += w0 * v0.w;
    }

    float4 bb = *(const float4*)&b2[c * 4];
    float4 r;
    r.x = a0.x + a1.x + bb.x;
    r.y = a0.y + a1.y + bb.y;
    r.z = a0.z + a1.z + bb.z;
    r.w = a0.w + a1.w + bb.w;
    *(float4*)&out[(size_t)d * NCLASS + c * 4] = r;
}

// ---------------------------------------------------------------------------
// kernel_launch
// inputs: 0=x 1=edge_src 2=edge_dst 3=edge_weight 4=W1 5=b1 6=W2 7=b2
// ---------------------------------------------------------------------------
extern "C" void kernel_launch(void* const* d_in, const int* in_sizes, int n_in,
                              void* d_out, int out_size)
{
    const float* x   = (const float*)d_in[0];
    const int*   es  = (const int*)d_in[1];
    const int*   ed  = (const int*)d_in[2];
    const float* ew  = (const float*)d_in[3];
    const float* W1  = (const float*)d_in[4];
    const float* b1  = (const float*)d_in[5];
    const float* W2  = (const float*)d_in[6];
    const float* b2  = (const float*)d_in[7];
    float* out = (float*)d_out;

    float *h1, *agg1, *h2;
    cudaGetSymbolAddress((void**)&h1,   g_h1);
    cudaGetSymbolAddress((void**)&agg1, g_agg1);
    cudaGetSymbolAddress((void**)&h2,   g_h2);

    const int M = N_NODES;

    // --- CSR build (dst-sorted edges), reused by both SpMM layers ---
    zero_count_kernel<<<(N_NODES + 255) / 256, 256>>>();
    hist_kernel<<<(N_EDGES + 255) / 256, 256>>>(ed);
    scan_kernel<<<1, 1024>>>();
    scatter_kernel<<<(N_EDGES + 255) / 256, 256>>>(es, ed, ew);

    // 1) support1 = x @ W1  (tf32 HMMA)
    gemm1_mma_kernel<<<(M + 127) / 128, 256>>>(x, W1, h1, M);

    // 2) agg1 = A @ h1 + b1   (CSR segmented sum, warp per dst)
    spmm1_csr_kernel<<<(N_NODES + 7) / 8, 256>>>(b1);

    // 3) support2 = relu(agg1) @ W2
    gemm2_kernel<<<(M + 127) / 128, 256>>>(agg1, W2, h2, M);

    // 4) out = A @ h2 + b2   (CSR segmented sum, 10 threads per dst)
    {
        size_t threads = (size_t)N_NODES * 10;
        spmm2_csr_kernel<<<(unsigned)((threads + 255) / 256), 256>>>(b2, out);
    }
}

// round 10
// speedup vs baseline: 1.8207x; 1.8207x over previous
#include <cuda_runtime.h>
#include <cuda_bf16.h>
#include <cstdint>

// Problem constants (fixed by the reference)
#define N_NODES 50000
#define N_EDGES 800000
#define NFEAT   512
#define NHID    128
#define NCLASS  40

#define EC      16                 // edges per chunk (800000 % 16 == 0)
#define N_CHUNK (N_EDGES / EC)     // 50000

// Device scratch (no cudaMalloc allowed)
__device__ float g_h1[N_NODES * NHID];    // support1 = x @ W1
__device__ float g_agg1[N_NODES * NHID];  // aggregated layer-1 out
__device__ float g_h2[N_NODES * NCLASS];  // support2 = relu(h) @ W2

// sort scratch
__device__ int   g_count[N_NODES];
__device__ int   g_rank[N_EDGES];
__device__ int   g_off[N_NODES];
#define N_BLK ((N_NODES + 255) / 256)     // 196
__device__ int   g_bsum[N_BLK];
__device__ int   g_bsum_ex[N_BLK];
__device__ int4  g_edge_s[N_EDGES];       // (src, w_bits, dst, 0) sorted by dst

__device__ __forceinline__ uint32_t cvt_tf32(float f) {
    uint32_t out;
    asm("cvt.rna.tf32.f32 %0, %1;" : "=r"(out) : "f"(f));
    return out;
}

__device__ __forceinline__ void mma_tf32(
    float& d0, float& d1, float& d2, float& d3,
    uint32_t a0, uint32_t a1, uint32_t a2, uint32_t a3,
    uint32_t b0, uint32_t b1)
{
    asm volatile(
        "mma.sync.aligned.m16n8k8.row.col.f32.tf32.tf32.f32 "
        "{%0,%1,%2,%3}, {%4,%5,%6,%7}, {%8,%9}, {%0,%1,%2,%3};"
        : "+f"(d0), "+f"(d1), "+f"(d2), "+f"(d3)
        : "r"(a0), "r"(a1), "r"(a2), "r"(a3), "r"(b0), "r"(b1));
}

__device__ __forceinline__ void red_add_v4(float* addr, float4 v)
{
    asm volatile("red.global.add.v4.f32 [%0], {%1, %2, %3, %4};"
                 :: "l"(addr), "f"(v.x), "f"(v.y), "f"(v.z), "f"(v.w)
                 : "memory");
}

// ===========================================================================
// GEMM1 (HMMA tf32): C[M,128] = tf32(A[M,512]) @ tf32(W1[512,128])
// ===========================================================================
#define G1_BK 32

__global__ __launch_bounds__(256) void gemm1_mma_kernel(
    const float* __restrict__ A, const float* __restrict__ W1,
    float* __restrict__ C, int M)
{
    __shared__ uint32_t sA[4 * 8 * 32 * 4];   // 16 KB
    __shared__ uint32_t sB[4 * 8 * 32 * 4];   // 16 KB

    const int tid  = threadIdx.x;
    const int lane = tid & 31;
    const int wid  = tid >> 5;
    const int warp_m = wid & 3;
    const int warp_n = wid >> 2;
    const int m0 = blockIdx.x * 128;

    float acc[2][8][4];
#pragma unroll
    for (int mi = 0; mi < 2; mi++)
#pragma unroll
        for (int nt = 0; nt < 8; nt++)
#pragma unroll
            for (int j = 0; j < 4; j++) acc[mi][nt][j] = 0.0f;

    for (int k0 = 0; k0 < NFEAT; k0 += G1_BK) {
#pragma unroll
        for (int t = 0; t < 4; t++) {
            int i = tid + t * 256;
            int r = i >> 3;
            int q = i & 7;
            float4 v = make_float4(0.f, 0.f, 0.f, 0.f);
            if (m0 + r < M)
                v = *(const float4*)&A[(size_t)(m0 + r) * NFEAT + k0 + q * 4];
            uint32_t u[4] = {cvt_tf32(v.x), cvt_tf32(v.y), cvt_tf32(v.z), cvt_tf32(v.w)};
            int ks   = q >> 1;
            int mt   = r >> 4;
            int slot = ((r >> 3) & 1) + 2 * (q & 1);
            int base = ((ks * 8 + mt) * 32 + (r & 7) * 4) * 4 + slot;
#pragma unroll
            for (int j = 0; j < 4; j++) sA[base + j * 4] = u[j];
        }
#pragma unroll
        for (int t = 0; t < 4; t++) {
            int i = tid + t * 256;
            int kk = i >> 5;
            int nf = i & 31;
            float4 v = *(const float4*)&W1[(size_t)(k0 + kk) * NHID + nf * 4];
            uint32_t u[4] = {cvt_tf32(v.x), cvt_tf32(v.y), cvt_tf32(v.z), cvt_tf32(v.w)};
            int ks   = kk >> 3;
            int kc   = kk & 7;
            int ntp  = nf >> 2;
            int slot = ((nf >> 1) & 1) * 2 + (kc >> 2);
            int base = ((ks * 8 + ntp) * 32 + (nf & 1) * 16 + (kc & 3)) * 4 + slot;
#pragma unroll
            for (int j = 0; j < 4; j++) sB[base + j * 16] = u[j];
        }
        __syncthreads();

#pragma unroll
        for (int ks = 0; ks < 4; ks++) {
            uint4 af[2];
#pragma unroll
            for (int mi = 0; mi < 2; mi++) {
                int mt = warp_m * 2 + mi;
                af[mi] = *(const uint4*)&sA[((ks * 8 + mt) * 32 + lane) * 4];
            }
#pragma unroll
            for (int np = 0; np < 4; np++) {
                int ntp = warp_n * 4 + np;
                uint4 bf = *(const uint4*)&sB[((ks * 8 + ntp) * 32 + lane) * 4];
#pragma unroll
                for (int mi = 0; mi < 2; mi++) {
                    mma_tf32(acc[mi][np*2][0], acc[mi][np*2][1],
                             acc[mi][np*2][2], acc[mi][np*2][3],
                             af[mi].x, af[mi].y, af[mi].z, af[mi].w,
                             bf.x, bf.y);
                    mma_tf32(acc[mi][np*2+1][0], acc[mi][np*2+1][1],
                             acc[mi][np*2+1][2], acc[mi][np*2+1][3],
                             af[mi].x, af[mi].y, af[mi].z, af[mi].w,
                             bf.z, bf.w);
                }
            }
        }
        __syncthreads();
    }

#pragma unroll
    for (int mi = 0; mi < 2; mi++) {
        int r_base = m0 + warp_m * 32 + mi * 16 + (lane >> 2);
#pragma unroll
        for (int nt = 0; nt < 8; nt++) {
            int col = warp_n * 64 + nt * 8 + (lane & 3) * 2;
            if (r_base < M)
                *(float2*)&C[(size_t)r_base * NHID + col] =
                    make_float2(acc[mi][nt][0], acc[mi][nt][1]);
            if (r_base + 8 < M)
                *(float2*)&C[(size_t)(r_base + 8) * NHID + col] =
                    make_float2(acc[mi][nt][2], acc[mi][nt][3]);
        }
    }
}

// ===========================================================================
// Sort build: zero -> hist(+rank) -> blocksum -> scan -> offsets -> scatter
// ===========================================================================
__global__ void zero_count_kernel()
{
    int i = blockIdx.x * blockDim.x + threadIdx.x;
    if (i < N_NODES) g_count[i] = 0;
}

__global__ void hist_kernel(const int* __restrict__ edst)
{
    int e = blockIdx.x * blockDim.x + threadIdx.x;
    if (e < N_EDGES) g_rank[e] = atomicAdd(&g_count[edst[e]], 1);
}

__global__ __launch_bounds__(256) void blocksum_kernel()
{
    __shared__ int ws[8];
    int i = blockIdx.x * 256 + threadIdx.x;
    int c = (i < N_NODES) ? g_count[i] : 0;
    int lane = threadIdx.x & 31, w = threadIdx.x >> 5;
    int v = c;
#pragma unroll
    for (int o = 16; o > 0; o >>= 1) v += __shfl_down_sync(0xFFFFFFFFu, v, o);
    if (lane == 0) ws[w] = v;
    __syncthreads();
    if (threadIdx.x == 0) {
        int s = 0;
#pragma unroll
        for (int j = 0; j < 8; j++) s += ws[j];
        g_bsum[blockIdx.x] = s;
    }
}

__global__ __launch_bounds__(256) void scan_bsum_kernel()
{
    __shared__ int sm[256];
    int tid = threadIdx.x;
    int v = (tid < N_BLK) ? g_bsum[tid] : 0;
    sm[tid] = v;
    __syncthreads();
#pragma unroll
    for (int o = 1; o < 256; o <<= 1) {
        int n = (tid >= o) ? sm[tid - o] : 0;
        __syncthreads();
        sm[tid] += n;
        __syncthreads();
    }
    if (tid < N_BLK) g_bsum_ex[tid] = sm[tid] - v;   // exclusive
}

__global__ __launch_bounds__(256) void offsets_kernel()
{
    __shared__ int sm[256];
    int tid = threadIdx.x;
    int i = blockIdx.x * 256 + tid;
    int c = (i < N_NODES) ? g_count[i] : 0;
    sm[tid] = c;
    __syncthreads();
#pragma unroll
    for (int o = 1; o < 256; o <<= 1) {
        int n = (tid >= o) ? sm[tid - o] : 0;
        __syncthreads();
        sm[tid] += n;
        __syncthreads();
    }
    if (i < N_NODES) g_off[i] = g_bsum_ex[blockIdx.x] + sm[tid] - c;
}

__global__ void scatter_kernel(const int* __restrict__ esrc,
                               const int* __restrict__ edst,
                               const float* __restrict__ ew)
{
    int e = blockIdx.x * blockDim.x + threadIdx.x;
    if (e >= N_EDGES) return;
    int d = edst[e];
    int pos = g_off[d] + g_rank[e];
    g_edge_s[pos] = make_int4(esrc[e], __float_as_int(ew[e]), d, 0);
}

// ---------------------------------------------------------------------------
// Bias-broadcast initializers (reductions land on top)
// ---------------------------------------------------------------------------
__global__ void init_bias128_kernel(float* __restrict__ dst,
                                    const float* __restrict__ b)
{
    __shared__ float sb[NHID];
    if (threadIdx.x < NHID) sb[threadIdx.x] = b[threadIdx.x];
    __syncthreads();
    size_t idx = (size_t)blockIdx.x * blockDim.x + threadIdx.x;
    size_t total = (size_t)N_NODES * NHID;
    if (idx < total) dst[idx] = sb[idx & (NHID - 1)];
}

__global__ void init_bias40_kernel(float* __restrict__ dst,
                                   const float* __restrict__ b)
{
    __shared__ float sb[NCLASS];
    if (threadIdx.x < NCLASS) sb[threadIdx.x] = b[threadIdx.x];
    __syncthreads();
    size_t idx = (size_t)blockIdx.x * blockDim.x + threadIdx.x;
    size_t total = (size_t)N_NODES * NCLASS;
    if (idx < total) dst[idx] = sb[idx % NCLASS];
}

// ===========================================================================
// SpMM layer 1: warp per 16-edge chunk of dst-sorted edges.
// Register accumulation across equal-dst runs; RED only at run boundaries.
// ===========================================================================
__global__ __launch_bounds__(256) void spmm1_seg_kernel()
{
    const int wid  = threadIdx.x >> 5;
    const int lane = threadIdx.x & 31;
    const int chunk = blockIdx.x * 8 + wid;
    if (chunk >= N_CHUNK) return;
    const int base = chunk * EC;

    float4 acc = make_float4(0.f, 0.f, 0.f, 0.f);
    int cur_d = g_edge_s[base].z;

#pragma unroll
    for (int i = 0; i < EC; i++) {
        int4 ed = g_edge_s[base + i];
        float4 v = *(const float4*)&g_h1[(size_t)ed.x * NHID + lane * 4];
        float w = __int_as_float(ed.y);
        if (ed.z != cur_d) {     // warp-uniform branch
            red_add_v4(&g_agg1[(size_t)cur_d * NHID + lane * 4], acc);
            acc = make_float4(0.f, 0.f, 0.f, 0.f);
            cur_d = ed.z;
        }
        acc.x += w * v.x; acc.y += w * v.y;
        acc.z += w * v.z; acc.w += w * v.w;
    }
    red_add_v4(&g_agg1[(size_t)cur_d * NHID + lane * 4], acc);
}

// ===========================================================================
// GEMM2: C[M,40] = relu(H[M,128]) @ W2[128,40]
// ===========================================================================
__global__ __launch_bounds__(256) void gemm2_kernel(
    const float* __restrict__ H, const float* __restrict__ W2,
    float* __restrict__ C, int M)
{
    __shared__ float sW[NHID * NCLASS];   // [k][c]  20 KB
    __shared__ float sh[32 * 128];        // [k][node] 16 KB

    const int tid = threadIdx.x;
    const int tx = tid & 7;
    const int ty = tid >> 3;
    const int n0 = blockIdx.x * 128;

    for (int i = tid; i < (NHID * NCLASS) / 4; i += 256)
        *(float4*)&sW[i * 4] = *(const float4*)&W2[i * 4];

    float acc[4][5];
#pragma unroll
    for (int i = 0; i < 4; i++)
#pragma unroll
        for (int j = 0; j < 5; j++) acc[i][j] = 0.0f;

    for (int kc = 0; kc < 4; kc++) {
        __syncthreads();
        for (int i = tid; i < 1024; i += 256) {
            int node = i & 127;
            int kq   = i >> 7;
            float4 v = make_float4(0.f, 0.f, 0.f, 0.f);
            if (n0 + node < M) {
                v = *(const float4*)&H[(size_t)(n0 + node) * NHID + kc * 32 + kq * 4];
                v.x = fmaxf(v.x, 0.f); v.y = fmaxf(v.y, 0.f);
                v.z = fmaxf(v.z, 0.f); v.w = fmaxf(v.w, 0.f);
            }
            sh[(kq * 4 + 0) * 128 + node] = v.x;
            sh[(kq * 4 + 1) * 128 + node] = v.y;
            sh[(kq * 4 + 2) * 128 + node] = v.z;
            sh[(kq * 4 + 3) * 128 + node] = v.w;
        }
        __syncthreads();

#pragma unroll
        for (int k = 0; k < 32; k++) {
            float4 h4 = *(const float4*)&sh[k * 128 + ty * 4];
            const float* wr = &sW[(kc * 32 + k) * NCLASS + tx];
#pragma unroll
            for (int j = 0; j < 5; j++) {
                float w = wr[j * 8];
                acc[0][j] += h4.x * w;
                acc[1][j] += h4.y * w;
                acc[2][j] += h4.z * w;
                acc[3][j] += h4.w * w;
            }
        }
    }

#pragma unroll
    for (int i = 0; i < 4; i++) {
        int node = n0 + ty * 4 + i;
        if (node < M) {
#pragma unroll
            for (int j = 0; j < 5; j++)
                C[(size_t)node * NCLASS + tx + j * 8] = acc[i][j];
        }
    }
}

// ===========================================================================
// SpMM layer 2: thread = (16-edge chunk, float4-chunk c of 10), run-compacted
// ===========================================================================
__global__ __launch_bounds__(256) void spmm2_seg_kernel(float* __restrict__ out)
{
    unsigned gid = blockIdx.x * blockDim.x + threadIdx.x;
    unsigned chunk = gid / 10;
    unsigned c = gid % 10;
    if (chunk >= N_CHUNK) return;
    const int base = chunk * EC;

    float4 acc = make_float4(0.f, 0.f, 0.f, 0.f);
    int cur_d = g_edge_s[base].z;

#pragma unroll
    for (int i = 0; i < EC; i++) {
        int4 ed = g_edge_s[base + i];
        float4 v = *(const float4*)&g_h2[(size_t)ed.x * NCLASS + c * 4];
        float w = __int_as_float(ed.y);
        if (ed.z != cur_d) {
            red_add_v4(&out[(size_t)cur_d * NCLASS + c * 4], acc);
            acc = make_float4(0.f, 0.f, 0.f, 0.f);
            cur_d = ed.z;
        }
        acc.x += w * v.x; acc.y += w * v.y;
        acc.z += w * v.z; acc.w += w * v.w;
    }
    red_add_v4(&out[(size_t)cur_d * NCLASS + c * 4], acc);
}

// ---------------------------------------------------------------------------
// kernel_launch
// inputs: 0=x 1=edge_src 2=edge_dst 3=edge_weight 4=W1 5=b1 6=W2 7=b2
// ---------------------------------------------------------------------------
extern "C" void kernel_launch(void* const* d_in, const int* in_sizes, int n_in,
                              void* d_out, int out_size)
{
    const float* x   = (const float*)d_in[0];
    const int*   es  = (const int*)d_in[1];
    const int*   ed  = (const int*)d_in[2];
    const float* ew  = (const float*)d_in[3];
    const float* W1  = (const float*)d_in[4];
    const float* b1  = (const float*)d_in[5];
    const float* W2  = (const float*)d_in[6];
    const float* b2  = (const float*)d_in[7];
    float* out = (float*)d_out;

    float *h1, *agg1, *h2;
    cudaGetSymbolAddress((void**)&h1,   g_h1);
    cudaGetSymbolAddress((void**)&agg1, g_agg1);
    cudaGetSymbolAddress((void**)&h2,   g_h2);

    const int M = N_NODES;

    // --- dst-sort build (no atomics in scatter; rank from hist) ---
    zero_count_kernel<<<(N_NODES + 255) / 256, 256>>>();
    hist_kernel<<<(N_EDGES + 255) / 256, 256>>>(ed);
    blocksum_kernel<<<N_BLK, 256>>>();
    scan_bsum_kernel<<<1, 256>>>();
    offsets_kernel<<<N_BLK, 256>>>();
    scatter_kernel<<<(N_EDGES + 255) / 256, 256>>>(es, ed, ew);

    // 1) support1 = x @ W1  (tf32 HMMA)
    gemm1_mma_kernel<<<(M + 127) / 128, 256>>>(x, W1, h1, M);

    // 2) agg1 = b1; += chunked segmented scatter-reduce
    {
        size_t total = (size_t)M * NHID;
        init_bias128_kernel<<<(unsigned)((total + 255) / 256), 256>>>(agg1, b1);
    }
    spmm1_seg_kernel<<<(N_CHUNK + 7) / 8, 256>>>();

    // 3) support2 = relu(agg1) @ W2
    gemm2_kernel<<<(M + 127) / 128, 256>>>(agg1, W2, h2, M);

    // 4) out = b2; += chunked segmented scatter-reduce
    {
        size_t total = (size_t)M * NCLASS;
        init_bias40_kernel<<<(unsigned)((total + 255) / 256), 256>>>(out, b2);
    }
    {
        size_t threads = (size_t)N_CHUNK * 10;
        spmm2_seg_kernel<<<(unsigned)((threads + 255) / 256), 256>>>(out);
    }
}

// round 12
// speedup vs baseline: 1.9198x; 1.0544x over previous
#include <cuda_runtime.h>
#include <cuda_bf16.h>
#include <cuda_fp16.h>
#include <cstdint>

// Problem constants (fixed by the reference)
#define N_NODES 50000
#define N_EDGES 800000
#define NFEAT   512
#define NHID    128
#define NCLASS  40

#define EC      16                 // edges per chunk (800000 % 16 == 0)
#define N_CHUNK (N_EDGES / EC)     // 50000

// Device scratch (no cudaMalloc allowed)
__device__ __half g_h1h[N_NODES * NHID];  // support1 = x @ W1 (fp16, 12.8 MB)
__device__ float g_agg1[N_NODES * NHID];  // aggregated layer-1 out
__device__ float g_h2[N_NODES * NCLASS];  // support2 = relu(h) @ W2

// sort scratch
__device__ int   g_count[N_NODES];
__device__ int   g_rank[N_EDGES];
__device__ int   g_off[N_NODES];
#define N_BLK ((N_NODES + 255) / 256)     // 196
__device__ int   g_bsum[N_BLK];
__device__ int4  g_edge_s[N_EDGES];       // (src, w_bits, dst, 0) sorted by dst

__device__ __forceinline__ uint32_t cvt_tf32(float f) {
    uint32_t out;
    asm("cvt.rna.tf32.f32 %0, %1;" : "=r"(out) : "f"(f));
    return out;
}

__device__ __forceinline__ void mma_tf32(
    float& d0, float& d1, float& d2, float& d3,
    uint32_t a0, uint32_t a1, uint32_t a2, uint32_t a3,
    uint32_t b0, uint32_t b1)
{
    asm volatile(
        "mma.sync.aligned.m16n8k8.row.col.f32.tf32.tf32.f32 "
        "{%0,%1,%2,%3}, {%4,%5,%6,%7}, {%8,%9}, {%0,%1,%2,%3};"
        : "+f"(d0), "+f"(d1), "+f"(d2), "+f"(d3)
        : "r"(a0), "r"(a1), "r"(a2), "r"(a3), "r"(b0), "r"(b1));
}

__device__ __forceinline__ void red_add_v4(float* addr, float4 v)
{
    asm volatile("red.global.add.v4.f32 [%0], {%1, %2, %3, %4};"
                 :: "l"(addr), "f"(v.x), "f"(v.y), "f"(v.z), "f"(v.w)
                 : "memory");
}

// ===========================================================================
// GEMM1 (HMMA tf32): h1h[M,128] = tf32(A[M,512]) @ tf32(W1[512,128]) -> fp16
// CTA tile 128x128, BK=32, 8 warps, warp tile 32(M) x 64(N), frag-permuted smem
// ===========================================================================
#define G1_BK 32

__global__ __launch_bounds__(256) void gemm1_mma_kernel(
    const float* __restrict__ A, const float* __restrict__ W1, int M)
{
    __shared__ uint32_t sA[4 * 8 * 32 * 4];   // 16 KB
    __shared__ uint32_t sB[4 * 8 * 32 * 4];   // 16 KB

    const int tid  = threadIdx.x;
    const int lane = tid & 31;
    const int wid  = tid >> 5;
    const int warp_m = wid & 3;
    const int warp_n = wid >> 2;
    const int m0 = blockIdx.x * 128;

    float acc[2][8][4];
#pragma unroll
    for (int mi = 0; mi < 2; mi++)
#pragma unroll
        for (int nt = 0; nt < 8; nt++)
#pragma unroll
            for (int j = 0; j < 4; j++) acc[mi][nt][j] = 0.0f;

    for (int k0 = 0; k0 < NFEAT; k0 += G1_BK) {
#pragma unroll
        for (int t = 0; t < 4; t++) {
            int i = tid + t * 256;
            int r = i >> 3;
            int q = i & 7;
            float4 v = make_float4(0.f, 0.f, 0.f, 0.f);
            if (m0 + r < M)
                v = *(const float4*)&A[(size_t)(m0 + r) * NFEAT + k0 + q * 4];
            uint32_t u[4] = {cvt_tf32(v.x), cvt_tf32(v.y), cvt_tf32(v.z), cvt_tf32(v.w)};
            int ks   = q >> 1;
            int mt   = r >> 4;
            int slot = ((r >> 3) & 1) + 2 * (q & 1);
            int base = ((ks * 8 + mt) * 32 + (r & 7) * 4) * 4 + slot;
#pragma unroll
            for (int j = 0; j < 4; j++) sA[base + j * 4] = u[j];
        }
#pragma unroll
        for (int t = 0; t < 4; t++) {
            int i = tid + t * 256;
            int kk = i >> 5;
            int nf = i & 31;
            float4 v = *(const float4*)&W1[(size_t)(k0 + kk) * NHID + nf * 4];
            uint32_t u[4] = {cvt_tf32(v.x), cvt_tf32(v.y), cvt_tf32(v.z), cvt_tf32(v.w)};
            int ks   = kk >> 3;
            int kc   = kk & 7;
            int ntp  = nf >> 2;
            int slot = ((nf >> 1) & 1) * 2 + (kc >> 2);
            int base = ((ks * 8 + ntp) * 32 + (nf & 1) * 16 + (kc & 3)) * 4 + slot;
#pragma unroll
            for (int j = 0; j < 4; j++) sB[base + j * 16] = u[j];
        }
        __syncthreads();

#pragma unroll
        for (int ks = 0; ks < 4; ks++) {
            uint4 af[2];
#pragma unroll
            for (int mi = 0; mi < 2; mi++) {
                int mt = warp_m * 2 + mi;
                af[mi] = *(const uint4*)&sA[((ks * 8 + mt) * 32 + lane) * 4];
            }
#pragma unroll
            for (int np = 0; np < 4; np++) {
                int ntp = warp_n * 4 + np;
                uint4 bf = *(const uint4*)&sB[((ks * 8 + ntp) * 32 + lane) * 4];
#pragma unroll
                for (int mi = 0; mi < 2; mi++) {
                    mma_tf32(acc[mi][np*2][0], acc[mi][np*2][1],
                             acc[mi][np*2][2], acc[mi][np*2][3],
                             af[mi].x, af[mi].y, af[mi].z, af[mi].w,
                             bf.x, bf.y);
                    mma_tf32(acc[mi][np*2+1][0], acc[mi][np*2+1][1],
                             acc[mi][np*2+1][2], acc[mi][np*2+1][3],
                             af[mi].x, af[mi].y, af[mi].z, af[mi].w,
                             bf.z, bf.w);
                }
            }
        }
        __syncthreads();
    }

    // epilogue -> fp16 h1
#pragma unroll
    for (int mi = 0; mi < 2; mi++) {
        int r_base = m0 + warp_m * 32 + mi * 16 + (lane >> 2);
#pragma unroll
        for (int nt = 0; nt < 8; nt++) {
            int col = warp_n * 64 + nt * 8 + (lane & 3) * 2;
            if (r_base < M)
                *(__half2*)&g_h1h[(size_t)r_base * NHID + col] =
                    __floats2half2_rn(acc[mi][nt][0], acc[mi][nt][1]);
            if (r_base + 8 < M)
                *(__half2*)&g_h1h[(size_t)(r_base + 8) * NHID + col] =
                    __floats2half2_rn(acc[mi][nt][2], acc[mi][nt][3]);
        }
    }
}

// ===========================================================================
// Sort build: zero -> hist(+rank) -> blocksum -> offsets(incl. bsum scan)
//             -> scatter
// ===========================================================================
__global__ void zero_count_kernel()
{
    int i = blockIdx.x * blockDim.x + threadIdx.x;
    if (i < N_NODES) g_count[i] = 0;
}

__global__ void hist_kernel(const int* __restrict__ edst)
{
    int e = blockIdx.x * blockDim.x + threadIdx.x;
    if (e < N_EDGES) g_rank[e] = atomicAdd(&g_count[edst[e]], 1);
}

__global__ __launch_bounds__(256) void blocksum_kernel()
{
    __shared__ int ws[8];
    int i = blockIdx.x * 256 + threadIdx.x;
    int c = (i < N_NODES) ? g_count[i] : 0;
    int lane = threadIdx.x & 31, w = threadIdx.x >> 5;
    int v = c;
#pragma unroll
    for (int o = 16; o > 0; o >>= 1) v += __shfl_down_sync(0xFFFFFFFFu, v, o);
    if (lane == 0) ws[w] = v;
    __syncthreads();
    if (threadIdx.x == 0) {
        int s = 0;
#pragma unroll
        for (int j = 0; j < 8; j++) s += ws[j];
        g_bsum[blockIdx.x] = s;
    }
}

// every block redundantly scans the 196 block sums, then scans its 256 counts
__global__ __launch_bounds__(256) void offsets_kernel()
{
    __shared__ int sb[256];
    __shared__ int sm[256];
    const int tid = threadIdx.x;

    int bsv = (tid < N_BLK) ? g_bsum[tid] : 0;
    sb[tid] = bsv;
    __syncthreads();
#pragma unroll
    for (int o = 1; o < 256; o <<= 1) {
        int n = (tid >= o) ? sb[tid - o] : 0;
        __syncthreads();
        sb[tid] += n;
        __syncthreads();
    }
    // exclusive prefix of this block
    int blk_excl = sb[blockIdx.x] - g_bsum[blockIdx.x];

    int i = blockIdx.x * 256 + tid;
    int c = (i < N_NODES) ? g_count[i] : 0;
    sm[tid] = c;
    __syncthreads();
#pragma unroll
    for (int o = 1; o < 256; o <<= 1) {
        int n = (tid >= o) ? sm[tid - o] : 0;
        __syncthreads();
        sm[tid] += n;
        __syncthreads();
    }
    if (i < N_NODES) g_off[i] = blk_excl + sm[tid] - c;
}

__global__ void scatter_kernel(const int* __restrict__ esrc,
                               const int* __restrict__ edst,
                               const float* __restrict__ ew)
{
    int e = blockIdx.x * blockDim.x + threadIdx.x;
    if (e >= N_EDGES) return;
    int d = edst[e];
    int pos = g_off[d] + g_rank[e];
    g_edge_s[pos] = make_int4(esrc[e], __float_as_int(ew[e]), d, 0);
}

// ---------------------------------------------------------------------------
// Bias-broadcast initializers (reductions land on top)
// ---------------------------------------------------------------------------
__global__ void init_bias128_kernel(float* __restrict__ dst,
                                    const float* __restrict__ b)
{
    __shared__ float sb[NHID];
    if (threadIdx.x < NHID) sb[threadIdx.x] = b[threadIdx.x];
    __syncthreads();
    size_t idx = (size_t)blockIdx.x * blockDim.x + threadIdx.x;
    size_t total = (size_t)N_NODES * NHID;
    if (idx < total) dst[idx] = sb[idx & (NHID - 1)];
}

__global__ void init_bias40_kernel(float* __restrict__ dst,
                                   const float* __restrict__ b)
{
    __shared__ float sb[NCLASS];
    if (threadIdx.x < NCLASS) sb[threadIdx.x] = b[threadIdx.x];
    __syncthreads();
    size_t idx = (size_t)blockIdx.x * blockDim.x + threadIdx.x;
    size_t total = (size_t)N_NODES * NCLASS;
    if (idx < total) dst[idx] = sb[idx % NCLASS];
}

// ===========================================================================
// SpMM layer 1: warp per 16-edge chunk of dst-sorted edges, fp16 gathers.
// Register accumulation across equal-dst runs; RED only at run boundaries.
// ===========================================================================
__global__ __launch_bounds__(256) void spmm1_seg_kernel()
{
    const int wid  = threadIdx.x >> 5;
    const int lane = threadIdx.x & 31;
    const int chunk = blockIdx.x * 8 + wid;
    if (chunk >= N_CHUNK) return;
    const int base = chunk * EC;

    float4 acc = make_float4(0.f, 0.f, 0.f, 0.f);
    int cur_d = g_edge_s[base].z;

#pragma unroll
    for (int i = 0; i < EC; i++) {
        int4 ed = g_edge_s[base + i];
        uint2 raw = *(const uint2*)&g_h1h[(size_t)ed.x * NHID + lane * 4];
        float w = __int_as_float(ed.y);
        if (ed.z != cur_d) {     // warp-uniform branch
            red_add_v4(&g_agg1[(size_t)cur_d * NHID + lane * 4], acc);
            acc = make_float4(0.f, 0.f, 0.f, 0.f);
            cur_d = ed.z;
        }
        float2 f0 = __half22float2(*(__half2*)&raw.x);
        float2 f1 = __half22float2(*(__half2*)&raw.y);
        acc.x += w * f0.x; acc.y += w * f0.y;
        acc.z += w * f1.x; acc.w += w * f1.y;
    }
    red_add_v4(&g_agg1[(size_t)cur_d * NHID + lane * 4], acc);
}

// ===========================================================================
// GEMM2 (HMMA tf32): C[M,40] = tf32(relu(H[M,128])) @ tf32(W2[128,40])
// CTA = 128 rows, 8 warps (warp = 16 rows x 40 cols), W2 staged once.
// ===========================================================================
__global__ __launch_bounds__(256) void gemm2_mma_kernel(
    const float* __restrict__ H, const float* __restrict__ W2,
    float* __restrict__ C, int M)
{
    __shared__ uint32_t sH[4 * 8 * 32 * 4];    // 16 KB [ks4][mt8][lane][slot]
    __shared__ uint32_t sW2[16 * 3 * 32 * 4];  // 24 KB [gks16][ntp3][lane][slot]

    const int tid  = threadIdx.x;
    const int lane = tid & 31;
    const int wid  = tid >> 5;      // mt = wid (16 rows each)
    const int m0 = blockIdx.x * 128;

    // stage W2 (1280 float4s), frag-permuted; pad slots (n>=40) never read
    for (int i = tid; i < 1280; i += 256) {
        int kk = i / 10;            // 0..127
        int nf = i % 10;            // n = nf*4 + j
        float4 v = *(const float4*)&W2[(size_t)kk * NCLASS + nf * 4];
        uint32_t u[4] = {cvt_tf32(v.x), cvt_tf32(v.y), cvt_tf32(v.z), cvt_tf32(v.w)};
        int gks  = kk >> 3;
        int kc   = kk & 7;
        int ntp  = nf >> 2;
        int slot = ((nf >> 1) & 1) * 2 + (kc >> 2);
        int base = ((gks * 3 + ntp) * 32 + (nf & 1) * 16 + (kc & 3)) * 4 + slot;
#pragma unroll
        for (int j = 0; j < 4; j++) sW2[base + j * 16] = u[j];
    }

    float acc[5][4];
#pragma unroll
    for (int nt = 0; nt < 5; nt++)
#pragma unroll
        for (int j = 0; j < 4; j++) acc[nt][j] = 0.0f;

    for (int kc4 = 0; kc4 < 4; kc4++) {
        __syncthreads();   // also covers sW2 staging on first iter
        // stage H chunk: 128 rows x 32 k, relu fused
#pragma unroll
        for (int t = 0; t < 4; t++) {
            int i = tid + t * 256;
            int r = i >> 3;
            int q = i & 7;
            float4 v = make_float4(0.f, 0.f, 0.f, 0.f);
            if (m0 + r < M) {
                v = *(const float4*)&H[(size_t)(m0 + r) * NHID + kc4 * 32 + q * 4];
                v.x = fmaxf(v.x, 0.f); v.y = fmaxf(v.y, 0.f);
                v.z = fmaxf(v.z, 0.f); v.w = fmaxf(v.w, 0.f);
            }
            uint32_t u[4] = {cvt_tf32(v.x), cvt_tf32(v.y), cvt_tf32(v.z), cvt_tf32(v.w)};
            int ks   = q >> 1;
            int mt   = r >> 4;
            int slot = ((r >> 3) & 1) + 2 * (q & 1);
            int base = ((ks * 8 + mt) * 32 + (r & 7) * 4) * 4 + slot;
#pragma unroll
            for (int j = 0; j < 4; j++) sH[base + j * 4] = u[j];
        }
        __syncthreads();

#pragma unroll
        for (int ks = 0; ks < 4; ks++) {
            int gks = kc4 * 4 + ks;
            uint4 af = *(const uint4*)&sH[((ks * 8 + wid) * 32 + lane) * 4];
            uint4 b0 = *(const uint4*)&sW2[((gks * 3 + 0) * 32 + lane) * 4];
            uint4 b1 = *(const uint4*)&sW2[((gks * 3 + 1) * 32 + lane) * 4];
            uint4 b2 = *(const uint4*)&sW2[((gks * 3 + 2) * 32 + lane) * 4];
            mma_tf32(acc[0][0], acc[0][1], acc[0][2], acc[0][3],
                     af.x, af.y, af.z, af.w, b0.x, b0.y);
            mma_tf32(acc[1][0], acc[1][1], acc[1][2], acc[1][3],
                     af.x, af.y, af.z, af.w, b0.z, b0.w);
            mma_tf32(acc[2][0], acc[2][1], acc[2][2], acc[2][3],
                     af.x, af.y, af.z, af.w, b1.x, b1.y);
            mma_tf32(acc[3][0], acc[3][1], acc[3][2], acc[3][3],
                     af.x, af.y, af.z, af.w, b1.z, b1.w);
            mma_tf32(acc[4][0], acc[4][1], acc[4][2], acc[4][3],
                     af.x, af.y, af.z, af.w, b2.x, b2.y);
        }
    }

    // epilogue
    int r = m0 + wid * 16 + (lane >> 2);
#pragma unroll
    for (int nt = 0; nt < 5; nt++) {
        int col = nt * 8 + (lane & 3) * 2;
        if (r < M)
            *(float2*)&C[(size_t)r * NCLASS + col] =
                make_float2(acc[nt][0], acc[nt][1]);
        if (r + 8 < M)
            *(float2*)&C[(size_t)(r + 8) * NCLASS + col] =
                make_float2(acc[nt][2], acc[nt][3]);
    }
}

// ===========================================================================
// SpMM layer 2: thread = (16-edge chunk, float4-chunk c of 10), run-compacted
// ===========================================================================
__global__ __launch_bounds__(256) void spmm2_seg_kernel(float* __restrict__ out)
{
    unsigned gid = blockIdx.x * blockDim.x + threadIdx.x;
    unsigned chunk = gid / 10;
    unsigned c = gid % 10;
    if (chunk >= N_CHUNK) return;
    const int base = chunk * EC;

    float4 acc = make_float4(0.f, 0.f, 0.f, 0.f);
    int cur_d = g_edge_s[base].z;

#pragma unroll
    for (int i = 0; i < EC; i++) {
        int4 ed = g_edge_s[base + i];
        float4 v = *(const float4*)&g_h2[(size_t)ed.x * NCLASS + c * 4];
        float w = __int_as_float(ed.y);
        if (ed.z != cur_d) {
            red_add_v4(&out[(size_t)cur_d * NCLASS + c * 4], acc);
            acc = make_float4(0.f, 0.f, 0.f, 0.f);
            cur_d = ed.z;
        }
        acc.x += w * v.x; acc.y += w * v.y;
        acc.z += w * v.z; acc.w += w * v.w;
    }
    red_add_v4(&out[(size_t)cur_d * NCLASS + c * 4], acc);
}

// ---------------------------------------------------------------------------
// kernel_launch
// inputs: 0=x 1=edge_src 2=edge_dst 3=edge_weight 4=W1 5=b1 6=W2 7=b2
// ---------------------------------------------------------------------------
extern "C" void kernel_launch(void* const* d_in, const int* in_sizes, int n_in,
                              void* d_out, int out_size)
{
    const float* x   = (const float*)d_in[0];
    const int*   es  = (const int*)d_in[1];
    const int*   ed  = (const int*)d_in[2];
    const float* ew  = (const float*)d_in[3];
    const float* W1  = (const float*)d_in[4];
    const float* b1  = (const float*)d_in[5];
    const float* W2  = (const float*)d_in[6];
    const float* b2  = (const float*)d_in[7];
    float* out = (float*)d_out;

    float *agg1, *h2;
    cudaGetSymbolAddress((void**)&agg1, g_agg1);
    cudaGetSymbolAddress((void**)&h2,   g_h2);

    const int M = N_NODES;

    // --- dst-sort build ---
    zero_count_kernel<<<(N_NODES + 255) / 256, 256>>>();
    hist_kernel<<<(N_EDGES + 255) / 256, 256>>>(ed);
    blocksum_kernel<<<N_BLK, 256>>>();
    offsets_kernel<<<N_BLK, 256>>>();
    scatter_kernel<<<(N_EDGES + 255) / 256, 256>>>(es, ed, ew);

    // 1) h1 = x @ W1  (tf32 HMMA, fp16 output)
    gemm1_mma_kernel<<<(M + 127) / 128, 256>>>(x, W1, M);

    // 2) agg1 = b1; += chunked segmented scatter-reduce (fp16 gathers)
    {
        size_t total = (size_t)M * NHID;
        init_bias128_kernel<<<(unsigned)((total + 255) / 256), 256>>>(agg1, b1);
    }
    spmm1_seg_kernel<<<(N_CHUNK + 7) / 8, 256>>>();

    // 3) h2 = relu(agg1) @ W2  (tf32 HMMA)
    gemm2_mma_kernel<<<(M + 127) / 128, 256>>>(agg1, W2, h2, M);

    // 4) out = b2; += chunked segmented scatter-reduce
    {
        size_t total = (size_t)M * NCLASS;
        init_bias40_kernel<<<(unsigned)((total + 255) / 256), 256>>>(out, b2);
    }
    {
        size_t threads = (size_t)N_CHUNK * 10;
        spmm2_seg_kernel<<<(unsigned)((threads + 255) / 256), 256>>>(out);
    }
}